// round 6
// baseline (speedup 1.0000x reference)
#include <cuda_runtime.h>

#define S    512
#define NA   180
#define NB   4
#define WS   38
#define QA   45            // angles per phase
#define PI_D 3.14159265358979323846

// filtered sinogram, batch-pair interleaved: [pair][a][s] = {e0, e1, d0, d1}
// e_b = w_b[s] + 0.5*d_b,  d_b = w_b[s+1] - w_b[s]
__device__ float4 g_xf4[2 * NA * S];

// ---------------------------------------------------------------------------
// Stage 1: ramp filter, register-sliding FIR (one block per (b,a), 64 thr).
// ---------------------------------------------------------------------------
#define OFFM(d) ((d) + ((1 + (d)) >> 3))
#define OFFP(d) ((d) + ((7 + (d)) >> 3))

__global__ void __launch_bounds__(64) filter_kernel(const float* __restrict__ x) {
    const int a = blockIdx.x % NA;
    const int b = blockIdx.x / NA;

    __shared__ float P[1736];
    __shared__ float sg[256];
    __shared__ float sw[S + 8];

    const int t = threadIdx.x;

    #pragma unroll
    for (int i = t; i < 512; i += 64) {
        P[i + (i >> 3)] = 0.0f;
        int j = i + 1024;
        P[j + (j >> 3)] = 0.0f;
    }
    #pragma unroll
    for (int i = t; i < S; i += 64) {
        int ii = i + 512;
        P[ii + (ii >> 3)] = x[(b * S + i) * NA + a];
    }
    #pragma unroll
    for (int i = t; i < 256; i += 64) {
        float dd = (float)(2 * i + 1);
        sg[i] = -2.0f / ((float)(PI_D * PI_D) * dd * dd);
    }
    __syncthreads();

    float acc[8];
    #pragma unroll
    for (int k = 0; k < 8; ++k)
        acc[k] = 0.5f * P[9 * t + 576 + k];

    float Am[16], Ap[16];
    int A0 = 9 * t + 1;
    int A1 = 9 * t + 1132;

    #pragma unroll
    for (int d0 = 0; d0 < 8; ++d0) {
        Am[d0] = P[A0 + OFFM(d0)];
        Ap[d0] = P[A1 + OFFP(16 + d0)];
    }

    #pragma unroll 1
    for (int g = 0; g < 32; ++g) {
        #pragma unroll
        for (int jj = 0; jj < 8; ++jj) {
            float gc = sg[255 - 8 * g - jj];
            #pragma unroll
            for (int k = 0; k < 8; ++k) {
                float av = Am[(2 * jj + k) & 15];
                float bv = Ap[(k - 2 * jj) & 15];
                acc[k] = fmaf(gc, av + bv, acc[k]);
            }
            Am[(2 * jj + 8) & 15]  = P[A0 + OFFM(2 * jj + 8)];
            Am[(2 * jj + 9) & 15]  = P[A0 + OFFM(2 * jj + 9)];
            Ap[(14 - 2 * jj) & 15] = P[A1 + OFFP(14 - 2 * jj)];
            Ap[(15 - 2 * jj) & 15] = P[A1 + OFFP(15 - 2 * jj)];
        }
        A0 += 18;
        A1 -= 18;
    }

    #pragma unroll
    for (int k = 0; k < 8; ++k)
        sw[8 * t + k] = acc[k];
    if (t == 0) sw[S] = 0.0f;
    __syncthreads();

    float4* o4 = &g_xf4[((b >> 1) * NA + a) * S];
    const int h = b & 1;
    #pragma unroll
    for (int k = 0; k < 8; ++k) {
        int s = 8 * t + k;
        float lo = sw[s];
        float d  = sw[s + 1] - lo;
        float* po = (float*)&o4[s];
        po[h]     = fmaf(0.5f, d, lo);
        po[2 + h] = d;
    }
}

// ---------------------------------------------------------------------------
// Stage 2: backprojection, batch-paired float4 windows, granular asm.
// Grid (16,32,2): 32x16 tile x one batch PAIR. 256 threads, 2 y-slots each.
// 4 phases x 45 angles of float4 windows (27.4KB) in smem.
// ---------------------------------------------------------------------------
__global__ void __launch_bounds__(256, 4) backproj_kernel(float* __restrict__ out) {
    __shared__ float4 win4[QA * WS];         // 27360 B
    __shared__ float4 consA[NA];             // {cs, cs, cz, cz}
    __shared__ float4 consB[NA];             // {ns, ns, 8ns, 8ns}
    __shared__ int    w0s[NA];

    const int tid  = threadIdx.x;
    const int pair = blockIdx.z;
    const int x0   = blockIdx.x * 32;
    const int y0   = blockIdx.y * 16;

    const int lane = tid & 31;
    const int w    = tid >> 5;
    const int x    = ((w & 3) << 3) + (lane & 7);        // 0..31
    const int yb   = (lane >> 3) + ((w >> 2) << 2);      // 0..7 (slots yb, yb+8)

    const int b0 = 2 * pair, b1 = 2 * pair + 1;
    const float invh = 2.0f / 511.0f;

    // ---- early out: tile fully outside the unit circle ----
    {
        float ux0 = fmaf((float)x0,        invh, -1.0f);
        float ux1 = fmaf((float)(x0 + 31), invh, -1.0f);
        float uy0 = fmaf((float)y0,        invh, -1.0f);
        float uy1 = fmaf((float)(y0 + 15), invh, -1.0f);
        float mx = (ux0 <= 0.0f && ux1 >= 0.0f) ? 0.0f : fminf(fabsf(ux0), fabsf(ux1));
        float my = (uy0 <= 0.0f && uy1 >= 0.0f) ? 0.0f : fminf(fabsf(uy0), fabsf(uy1));
        if (mx * mx + my * my > 1.0f) {
            #pragma unroll
            for (int k = 0; k < 2; ++k) {
                int y = y0 + yb + 8 * k;
                out[(b0 * S + y) * S + x0 + x] = 0.0f;
                out[(b1 * S + y) * S + x0 + x] = 0.0f;
            }
            return;
        }
    }

    // ---- per-angle tables ----
    if (tid < NA) {
        float th = (float)tid * (float)(PI_D / 180.0);
        float sn, cs;
        sincosf(th, &sn, &cs);
        float pb = 255.5f + ((float)x0 - 255.5f) * cs - ((float)y0 - 255.5f) * sn;
        float pmin = pb + fminf(cs * 31.0f, 0.0f) + fminf(-sn * 15.0f, 0.0f);
        int w0 = (int)floorf(pmin) - 1;           // local p in [1, ~36.5)
        w0s[tid] = w0;
        float cz = pb - (float)w0 - 0.5f;
        float ns = -sn;
        consA[tid] = make_float4(cs, cs, cz, cz);
        consB[tid] = make_float4(ns, ns, 8.0f * ns, 8.0f * ns);
    }
    __syncthreads();

    // ---- packed per-thread constants ----
    unsigned long long FX2, FY2;
    {
        float fx = (float)x, fy = (float)yb;
        asm("mov.b64 %0, {%1, %1};" : "=l"(FX2) : "f"(fx));
        asm("mov.b64 %0, {%1, %1};" : "=l"(FY2) : "f"(fy));
    }
    const unsigned long long MAG2  = 0x4B0000004B000000ull;
    const unsigned long long NMAG2 = 0xCB000000CB000000ull;
    const unsigned long long NONE2 = 0xBF800000BF800000ull;

    // addr = wb + m*16, m = 0x4B000000 + idx -> fold 0x4B000000*16 mod 2^32
    const unsigned wbase0 = (unsigned)__cvta_generic_to_shared(win4) - 0xB0000000u;
    const unsigned cA0 = (unsigned)__cvta_generic_to_shared(consA);
    const unsigned cB0 = (unsigned)__cvta_generic_to_shared(consB);

    unsigned long long aE0 = 0, aF0 = 0, aE1 = 0, aF1 = 0;

    const float4* __restrict__ grow4 = &g_xf4[pair * NA * S];

    const int al = (tid < 228) ? tid / WS : 0;     // 0..5
    const int oo = tid - al * WS;

    #pragma unroll 1
    for (int phase = 0; phase < 4; ++phase) {
        const int abase = phase * QA;

        // ---- cooperative window fill (straight float4 copy) ----
        if (tid < 228) {
            #pragma unroll
            for (int ar = al; ar < QA; ar += 6) {
                int a  = abase + ar;
                int gi = w0s[a] + oo;
                float4 v;
                if ((unsigned)gi < (unsigned)S) {
                    v = grow4[a * S + gi];
                } else if (gi == -1) {
                    float4 v0 = grow4[a * S];
                    float w00 = v0.x - 0.5f * v0.z;
                    float w01 = v0.y - 0.5f * v0.w;
                    v = make_float4(0.5f * w00, 0.5f * w01, w00, w01);
                } else {
                    v = make_float4(0.0f, 0.0f, 0.0f, 0.0f);
                }
                win4[ar * WS + oo] = v;
            }
        }
        __syncthreads();

        unsigned caA = cA0 + (unsigned)abase * 16u;
        unsigned caB = cB0 + (unsigned)abase * 16u;
        unsigned wb  = wbase0;

        #pragma unroll 3
        for (int a = 0; a < QA; ++a) {
            unsigned m0, m1;
            unsigned long long FR0, FR1;

            // ---- front-end: addresses + packed {fr,fr} for 2 slots ----
            asm("{\n\t"
                ".reg .b64 XCS, XCZ, XNS, XN8, BX, TP0, TP1, TPM, TFL;\n\t"
                ".reg .b32 mt;\n\t"
                "ld.shared.v2.b64 {XCS, XCZ}, [%4];\n\t"
                "ld.shared.v2.b64 {XNS, XN8}, [%5];\n\t"
                "fma.rn.f32x2 BX, XCS, %6, XCZ;\n\t"
                "fma.rn.f32x2 TP0, XNS, %7, BX;\n\t"
                "add.rn.f32x2 TP1, TP0, XN8;\n\t"

                "add.rn.f32x2 TPM, TP0, %8;\n\t"
                "mov.b64 {%0, mt}, TPM;\n\t"
                "add.rn.f32x2 TFL, TPM, %9;\n\t"
                "fma.rn.f32x2 %2, TFL, %10, TP0;\n\t"
                "mad.lo.u32 %0, %0, 16, %11;\n\t"

                "add.rn.f32x2 TPM, TP1, %8;\n\t"
                "mov.b64 {%1, mt}, TPM;\n\t"
                "add.rn.f32x2 TFL, TPM, %9;\n\t"
                "fma.rn.f32x2 %3, TFL, %10, TP1;\n\t"
                "mad.lo.u32 %1, %1, 16, %11;\n\t"
                "}"
                : "=r"(m0), "=r"(m1), "=l"(FR0), "=l"(FR1)
                : "r"(caA), "r"(caB), "l"(FX2), "l"(FY2),
                  "l"(MAG2), "l"(NMAG2), "l"(NONE2), "r"(wb));

            // ---- 2 loads back-to-back ----
            unsigned long long E0, D0, E1, D1;
            asm volatile("ld.shared.v2.b64 {%0, %1}, [%2];" : "=l"(E0), "=l"(D0) : "r"(m0));
            asm volatile("ld.shared.v2.b64 {%0, %1}, [%2];" : "=l"(E1), "=l"(D1) : "r"(m1));

            // ---- accumulate (independent chains) ----
            asm("add.rn.f32x2 %0, %0, %1;" : "+l"(aE0) : "l"(E0));
            asm("fma.rn.f32x2 %0, %1, %2, %0;" : "+l"(aF0) : "l"(FR0), "l"(D0));
            asm("add.rn.f32x2 %0, %0, %1;" : "+l"(aE1) : "l"(E1));
            asm("fma.rn.f32x2 %0, %1, %2, %0;" : "+l"(aF1) : "l"(FR1), "l"(D1));

            caA += 16u;
            caB += 16u;
            wb  += (unsigned)(WS * 16);
        }
        __syncthreads();
    }

    // ---- unpack, mask, scale, store (both batches) ----
    const float scale = (float)(PI_D / (2.0 * NA));
    const float ux  = fmaf((float)(x0 + x), invh, -1.0f);
    const float uxx = ux * ux;

#define STORE_SLOT(AE, AF, K)                                                 \
    {                                                                         \
        float e_lo, e_hi, f_lo, f_hi;                                         \
        asm("mov.b64 {%0, %1}, %2;" : "=f"(e_lo), "=f"(e_hi) : "l"(AE));      \
        asm("mov.b64 {%0, %1}, %2;" : "=f"(f_lo), "=f"(f_hi) : "l"(AF));      \
        int y = y0 + yb + 8 * (K);                                            \
        float uy = fmaf((float)y, invh, -1.0f);                               \
        bool in = (uxx + uy * uy <= 1.0f);                                    \
        out[(b0 * S + y) * S + x0 + x] = in ? (e_lo + f_lo) * scale : 0.0f;   \
        out[(b1 * S + y) * S + x0 + x] = in ? (e_hi + f_hi) * scale : 0.0f;   \
    }

    STORE_SLOT(aE0, aF0, 0)
    STORE_SLOT(aE1, aF1, 1)
#undef STORE_SLOT
}

// ---------------------------------------------------------------------------
extern "C" void kernel_launch(void* const* d_in, const int* in_sizes, int n_in,
                              void* d_out, int out_size) {
    const float* x = (const float*)d_in[0];
    float* out = (float*)d_out;

    filter_kernel<<<NB * NA, 64>>>(x);

    dim3 grid(16, 32, 2);
    backproj_kernel<<<grid, 256>>>(out);
}

// round 12
// speedup vs baseline: 1.8205x; 1.8205x over previous
#include <cuda_runtime.h>
#include <cuda_fp16.h>

#define S    512
#define NA   180
#define NB   4
#define WS   38
#define HALF_A 90
#define PI_D 3.14159265358979323846

// filtered sinogram, batch-pair fp16: [pair][a][s] = uint2 { half2{em0,em1}, half2{d0,d1} }
// d = rn16(w[s+1]-w[s]),  em = rn16(w[s] + 0.5*float(d))
// sample = em + (fr-0.5)*d = w + fr*d   (f32 arithmetic; d errors damped by |fr-0.5|<=0.5)
__device__ uint2 g_xfh[2 * NA * S];

// ---------------------------------------------------------------------------
// Stage 1: ramp filter, register-sliding FIR (one block per (b,a), 64 thr).
// ---------------------------------------------------------------------------
#define OFFM(d) ((d) + ((1 + (d)) >> 3))
#define OFFP(d) ((d) + ((7 + (d)) >> 3))

__global__ void __launch_bounds__(64) filter_kernel(const float* __restrict__ x) {
    const int a = blockIdx.x % NA;
    const int b = blockIdx.x / NA;

    __shared__ float P[1736];
    __shared__ float sg[256];
    __shared__ float sw[S + 8];

    const int t = threadIdx.x;

    #pragma unroll
    for (int i = t; i < 512; i += 64) {
        P[i + (i >> 3)] = 0.0f;
        int j = i + 1024;
        P[j + (j >> 3)] = 0.0f;
    }
    #pragma unroll
    for (int i = t; i < S; i += 64) {
        int ii = i + 512;
        P[ii + (ii >> 3)] = x[(b * S + i) * NA + a];
    }
    #pragma unroll
    for (int i = t; i < 256; i += 64) {
        float dd = (float)(2 * i + 1);
        sg[i] = -2.0f / ((float)(PI_D * PI_D) * dd * dd);
    }
    __syncthreads();

    float acc[8];
    #pragma unroll
    for (int k = 0; k < 8; ++k)
        acc[k] = 0.5f * P[9 * t + 576 + k];

    float Am[16], Ap[16];
    int A0 = 9 * t + 1;
    int A1 = 9 * t + 1132;

    #pragma unroll
    for (int d0 = 0; d0 < 8; ++d0) {
        Am[d0] = P[A0 + OFFM(d0)];
        Ap[d0] = P[A1 + OFFP(16 + d0)];
    }

    #pragma unroll 1
    for (int g = 0; g < 32; ++g) {
        #pragma unroll
        for (int jj = 0; jj < 8; ++jj) {
            float gc = sg[255 - 8 * g - jj];
            #pragma unroll
            for (int k = 0; k < 8; ++k) {
                float av = Am[(2 * jj + k) & 15];
                float bv = Ap[(k - 2 * jj) & 15];
                acc[k] = fmaf(gc, av + bv, acc[k]);
            }
            Am[(2 * jj + 8) & 15]  = P[A0 + OFFM(2 * jj + 8)];
            Am[(2 * jj + 9) & 15]  = P[A0 + OFFM(2 * jj + 9)];
            Ap[(14 - 2 * jj) & 15] = P[A1 + OFFP(14 - 2 * jj)];
            Ap[(15 - 2 * jj) & 15] = P[A1 + OFFP(15 - 2 * jj)];
        }
        A0 += 18;
        A1 -= 18;
    }

    #pragma unroll
    for (int k = 0; k < 8; ++k)
        sw[8 * t + k] = acc[k];
    if (t == 0) sw[S] = 0.0f;
    __syncthreads();

    // write fp16 {em = w + 0.5*d16, d16} into our batch's 16-bit lanes.
    __half* ob = (__half*)&g_xfh[((b >> 1) * NA + a) * S];
    const int h = b & 1;
    #pragma unroll
    for (int k = 0; k < 8; ++k) {
        int s = 8 * t + k;
        float lo = sw[s];
        __half dh = __float2half(sw[s + 1] - lo);
        ob[s * 4 + h]     = __float2half(fmaf(0.5f, __half2float(dh), lo));
        ob[s * 4 + 2 + h] = dh;
    }
}

// ---------------------------------------------------------------------------
// Stage 2: backprojection, fp16 storage / f32 arithmetic.
// Grid (16,32,2): 32x16 tile x one batch PAIR. 256 threads, 2 y-slots each.
// p biased by +1024: bits>>13 = 0x22400+idx; fr (13 bits) -> exact f32 (1+fr)
// via shl+lop3; fm = fr-0.5 (Sterbenz-exact). sample = em + fm*d in f32.
// ---------------------------------------------------------------------------
__global__ void __launch_bounds__(256, 5) backproj_kernel(float* __restrict__ out) {
    __shared__ uint2  winh[HALF_A * WS];     // 27360 B
    __shared__ float4 consA[NA];             // {cs, czb, ns, 8ns}
    __shared__ int    w0s[NA];

    const int tid  = threadIdx.x;
    const int pair = blockIdx.z;
    const int x0   = blockIdx.x * 32;
    const int y0   = blockIdx.y * 16;

    const int lane = tid & 31;
    const int w    = tid >> 5;
    const int x    = ((w & 3) << 3) + (lane & 7);        // 0..31
    const int yb   = (lane >> 3) + ((w >> 2) << 2);      // 0..7 (slots yb, yb+8)

    const int b0 = 2 * pair, b1 = 2 * pair + 1;
    const float invh = 2.0f / 511.0f;

    // ---- early out: tile fully outside the unit circle ----
    {
        float ux0 = fmaf((float)x0,        invh, -1.0f);
        float ux1 = fmaf((float)(x0 + 31), invh, -1.0f);
        float uy0 = fmaf((float)y0,        invh, -1.0f);
        float uy1 = fmaf((float)(y0 + 15), invh, -1.0f);
        float mx = (ux0 <= 0.0f && ux1 >= 0.0f) ? 0.0f : fminf(fabsf(ux0), fabsf(ux1));
        float my = (uy0 <= 0.0f && uy1 >= 0.0f) ? 0.0f : fminf(fabsf(uy0), fabsf(uy1));
        if (mx * mx + my * my > 1.0f) {
            #pragma unroll
            for (int k = 0; k < 2; ++k) {
                int y = y0 + yb + 8 * k;
                out[(b0 * S + y) * S + x0 + x] = 0.0f;
                out[(b1 * S + y) * S + x0 + x] = 0.0f;
            }
            return;
        }
    }

    // ---- per-angle tables ----
    if (tid < NA) {
        float th = (float)tid * (float)(PI_D / 180.0);
        float sn, cs;
        sincosf(th, &sn, &cs);
        float pb = 255.5f + ((float)x0 - 255.5f) * cs - ((float)y0 - 255.5f) * sn;
        float pmin = pb + fminf(cs * 31.0f, 0.0f) + fminf(-sn * 15.0f, 0.0f);
        int w0 = (int)floorf(pmin) - 1;          // local p in [1, ~36.5)
        w0s[tid] = w0;
        float ns = -sn;
        consA[tid] = make_float4(cs, pb - (float)w0 + 1024.0f, ns, 8.0f * ns);
    }
    __syncthreads();

    const float FX = (float)x;
    const float FY = (float)yb;

    // addr = (bits>>13)*8 + wb ; bits>>13 = 0x22400 + idx -> wb0 = base - 0x112000
    const unsigned wbadj = (unsigned)__cvta_generic_to_shared(winh) - 0x112000u;
    const unsigned cA0 = (unsigned)__cvta_generic_to_shared(consA);

    float aE0 = 0.f, aE1 = 0.f, aF0 = 0.f, aF1 = 0.f;   // slot0 batches
    float bE0 = 0.f, bE1 = 0.f, bF0 = 0.f, bF1 = 0.f;   // slot1 batches

    const uint2* __restrict__ gw = &g_xfh[pair * NA * S];

    const int al = (tid < 228) ? tid / WS : 0;     // 0..5
    const int oo = tid - al * WS;

    #pragma unroll 1
    for (int phase = 0; phase < 2; ++phase) {
        const int abase = phase * HALF_A;

        // ---- cooperative window fill (straight uint2 copy) ----
        if (tid < 228) {
            #pragma unroll
            for (int ar = al; ar < HALF_A; ar += 6) {
                int a  = abase + ar;
                int gi = w0s[a] + oo;
                uint2 v;
                if ((unsigned)gi < (unsigned)S) {
                    v = gw[a * S + gi];
                } else if (gi == -1) {
                    // bin -1 interpolates 0 -> w[0]:  d = rn(w0), em = rn(0.5*d)
                    uint2 v0 = gw[a * S];
                    __half2 e2 = *(__half2*)&v0.x;   // em(0) = w0 + 0.5*d(0)
                    __half2 d2 = *(__half2*)&v0.y;
                    float w00 = __low2float(e2)  - 0.5f * __low2float(d2);
                    float w01 = __high2float(e2) - 0.5f * __high2float(d2);
                    __half2 nd = __floats2half2_rn(w00, w01);
                    __half2 ne = __floats2half2_rn(0.5f * __low2float(nd),
                                                   0.5f * __high2float(nd));
                    v.x = *(unsigned*)&ne;
                    v.y = *(unsigned*)&nd;
                } else {
                    v.x = 0u; v.y = 0u;
                }
                winh[ar * WS + oo] = v;
            }
        }
        __syncthreads();

        unsigned caA = cA0 + (unsigned)abase * 16u;
        unsigned wb  = wbadj;                      // per-angle window base

        #pragma unroll 3
        for (int a = 0; a < HALF_A; ++a) {
            unsigned a0, a1;
            float fm0, fm1;

            // ---- scalar front-end: biased p -> addr + f32 (fr-0.5) ----
            asm("{\n\t"
                ".reg .f32 cs, czb, ns, ns8, bx, p0f, p1f, ft;\n\t"
                ".reg .b32 rb0, rb1, rt;\n\t"
                "ld.shared.v4.f32 {cs, czb, ns, ns8}, [%4];\n\t"
                "fma.rn.f32 bx, cs, %5, czb;\n\t"
                "fma.rn.f32 p0f, ns, %6, bx;\n\t"
                "add.rn.f32 p1f, p0f, ns8;\n\t"
                "mov.b32 rb0, p0f;\n\t"
                "mov.b32 rb1, p1f;\n\t"
                "shr.u32 rt, rb0, 13;\n\t"
                "mad.lo.u32 %0, rt, 8, %7;\n\t"
                "shr.u32 rt, rb1, 13;\n\t"
                "mad.lo.u32 %1, rt, 8, %7;\n\t"
                "shl.b32 rt, rb0, 10;\n\t"
                "lop3.b32 rt, rt, 0x007FFC00, 0x3F800000, 0xEA;\n\t"
                "mov.b32 ft, rt;\n\t"
                "sub.rn.f32 %2, ft, 0f3FC00000;\n\t"    // (1+fr) - 1.5
                "shl.b32 rt, rb1, 10;\n\t"
                "lop3.b32 rt, rt, 0x007FFC00, 0x3F800000, 0xEA;\n\t"
                "mov.b32 ft, rt;\n\t"
                "sub.rn.f32 %3, ft, 0f3FC00000;\n\t"
                "}"
                : "=&r"(a0), "=&r"(a1), "=&f"(fm0), "=&f"(fm1)
                : "r"(caA), "f"(FX), "f"(FY), "r"(wb));

            // ---- 2 loads back-to-back ----
            unsigned E0, D0, E1, D1;
            asm volatile("ld.shared.v2.b32 {%0, %1}, [%2];" : "=r"(E0), "=r"(D0) : "r"(a0));
            asm volatile("ld.shared.v2.b32 {%0, %1}, [%2];" : "=r"(E1), "=r"(D1) : "r"(a1));

            // ---- f32 interpolate + accumulate ----
#define SLOT_ACC(FM, EE, DD, AE0, AE1, AF0, AF1)                              \
            asm("{\n\t"                                                       \
                ".reg .b16 hl, hh;\n\t"                                       \
                ".reg .f32 f0, f1, g0, g1;\n\t"                               \
                "mov.b32 {hl, hh}, %4;\n\t"                                   \
                "cvt.f32.f16 f0, hl;\n\t"                                     \
                "cvt.f32.f16 f1, hh;\n\t"                                     \
                "mov.b32 {hl, hh}, %5;\n\t"                                   \
                "cvt.f32.f16 g0, hl;\n\t"                                     \
                "cvt.f32.f16 g1, hh;\n\t"                                     \
                "add.rn.f32 %0, %0, f0;\n\t"                                  \
                "add.rn.f32 %1, %1, f1;\n\t"                                  \
                "fma.rn.f32 %2, %6, g0, %2;\n\t"                              \
                "fma.rn.f32 %3, %6, g1, %3;\n\t"                              \
                "}"                                                           \
                : "+f"(AE0), "+f"(AE1), "+f"(AF0), "+f"(AF1)                  \
                : "r"(EE), "r"(DD), "f"(FM));

            SLOT_ACC(fm0, E0, D0, aE0, aE1, aF0, aF1)
            SLOT_ACC(fm1, E1, D1, bE0, bE1, bF0, bF1)
#undef SLOT_ACC

            caA += 16u;
            wb  += (unsigned)(WS * 8);             // advance one window row
        }
        __syncthreads();
    }

    // ---- mask, scale, store (both batches) ----
    const float scale = (float)(PI_D / (2.0 * NA));
    const float ux  = fmaf((float)(x0 + x), invh, -1.0f);
    const float uxx = ux * ux;

    {
        int y = y0 + yb;
        float uy = fmaf((float)y, invh, -1.0f);
        bool in = (uxx + uy * uy <= 1.0f);
        out[(b0 * S + y) * S + x0 + x] = in ? (aE0 + aF0) * scale : 0.0f;
        out[(b1 * S + y) * S + x0 + x] = in ? (aE1 + aF1) * scale : 0.0f;
    }
    {
        int y = y0 + yb + 8;
        float uy = fmaf((float)y, invh, -1.0f);
        bool in = (uxx + uy * uy <= 1.0f);
        out[(b0 * S + y) * S + x0 + x] = in ? (bE0 + bF0) * scale : 0.0f;
        out[(b1 * S + y) * S + x0 + x] = in ? (bE1 + bF1) * scale : 0.0f;
    }
}

// ---------------------------------------------------------------------------
extern "C" void kernel_launch(void* const* d_in, const int* in_sizes, int n_in,
                              void* d_out, int out_size) {
    const float* x = (const float*)d_in[0];
    float* out = (float*)d_out;

    filter_kernel<<<NB * NA, 64>>>(x);

    dim3 grid(16, 32, 2);
    backproj_kernel<<<grid, 256>>>(out);
}

// round 13
// speedup vs baseline: 1.9231x; 1.0564x over previous
#include <cuda_runtime.h>
#include <cuda_fp16.h>

#define S    512
#define NA   180
#define NB   4
#define WS   38
#define HALF_A 90
#define PI_D 3.14159265358979323846

// filtered sinogram, batch-pair fp16: [pair][a][s] = uint2 { half2{em0,em1}, half2{d0,d1} }
// d = rn16(w[s+1]-w[s]),  em = rn16(w[s] + 0.5*float(d))
// sample = em + (fr-0.5)*d = w + fr*d   (f32 arithmetic)
__device__ uint2 g_xfh[2 * NA * S];

// ---------------------------------------------------------------------------
// Stage 1: ramp filter. One block per (pair, a): 128 threads = two independent
// 64-thread FIR halves (batch 2p, 2p+1), then a coalesced uint2 epilogue.
// ---------------------------------------------------------------------------
#define OFFM(d) ((d) + ((1 + (d)) >> 3))
#define OFFP(d) ((d) + ((7 + (d)) >> 3))

__global__ void __launch_bounds__(128) filter_kernel(const float* __restrict__ x) {
    const int a    = blockIdx.x % NA;
    const int pair = blockIdx.x / NA;

    __shared__ float P[2][1736];
    __shared__ float sg[256];
    __shared__ float sw[2][S + 8];

    const int tid  = threadIdx.x;
    const int half = tid >> 6;
    const int t    = tid & 63;
    const int b    = 2 * pair + half;
    float* Pb = P[half];

    #pragma unroll
    for (int i = t; i < 512; i += 64) {
        Pb[i + (i >> 3)] = 0.0f;
        int j = i + 1024;
        Pb[j + (j >> 3)] = 0.0f;
    }
    #pragma unroll
    for (int i = t; i < S; i += 64) {
        int ii = i + 512;
        Pb[ii + (ii >> 3)] = x[(b * S + i) * NA + a];
    }
    #pragma unroll
    for (int i = tid; i < 256; i += 128) {
        float dd = (float)(2 * i + 1);
        sg[i] = -2.0f / ((float)(PI_D * PI_D) * dd * dd);
    }
    __syncthreads();

    float acc[8];
    #pragma unroll
    for (int k = 0; k < 8; ++k)
        acc[k] = 0.5f * Pb[9 * t + 576 + k];

    float Am[16], Ap[16];
    int A0 = 9 * t + 1;
    int A1 = 9 * t + 1132;

    #pragma unroll
    for (int d0 = 0; d0 < 8; ++d0) {
        Am[d0] = Pb[A0 + OFFM(d0)];
        Ap[d0] = Pb[A1 + OFFP(16 + d0)];
    }

    #pragma unroll 1
    for (int g = 0; g < 32; ++g) {
        #pragma unroll
        for (int jj = 0; jj < 8; ++jj) {
            float gc = sg[255 - 8 * g - jj];
            #pragma unroll
            for (int k = 0; k < 8; ++k) {
                float av = Am[(2 * jj + k) & 15];
                float bv = Ap[(k - 2 * jj) & 15];
                acc[k] = fmaf(gc, av + bv, acc[k]);
            }
            Am[(2 * jj + 8) & 15]  = Pb[A0 + OFFM(2 * jj + 8)];
            Am[(2 * jj + 9) & 15]  = Pb[A0 + OFFM(2 * jj + 9)];
            Ap[(14 - 2 * jj) & 15] = Pb[A1 + OFFP(14 - 2 * jj)];
            Ap[(15 - 2 * jj) & 15] = Pb[A1 + OFFP(15 - 2 * jj)];
        }
        A0 += 18;
        A1 -= 18;
    }

    #pragma unroll
    for (int k = 0; k < 8; ++k)
        sw[half][8 * t + k] = acc[k];
    if (t == 0) sw[half][S] = 0.0f;
    __syncthreads();

    // cooperative coalesced epilogue: uint2 {em0,em1 | d0,d1}
    uint2* o = &g_xfh[(pair * NA + a) * S];
    #pragma unroll
    for (int s = tid; s < S; s += 128) {
        float lo0 = sw[0][s];
        float lo1 = sw[1][s];
        __half d0 = __float2half(sw[0][s + 1] - lo0);
        __half d1 = __float2half(sw[1][s + 1] - lo1);
        __half e0 = __float2half(fmaf(0.5f, __half2float(d0), lo0));
        __half e1 = __float2half(fmaf(0.5f, __half2float(d1), lo1));
        __half2 eh = __halves2half2(e0, e1);
        __half2 dh = __halves2half2(d0, d1);
        uint2 v;
        v.x = *(unsigned*)&eh;
        v.y = *(unsigned*)&dh;
        o[s] = v;
    }
}

// ---------------------------------------------------------------------------
// Stage 2: backprojection, fp16 storage / f32 arithmetic, packed E-accum.
// Grid (16,32,2): 32x16 tile x one batch PAIR. 256 threads, 2 y-slots each.
// ---------------------------------------------------------------------------
__global__ void __launch_bounds__(256, 6) backproj_kernel(float* __restrict__ out) {
    __shared__ uint2  winh[HALF_A * WS];     // 27360 B
    __shared__ float4 consA[NA];             // {cs, czb, ns, 8ns}
    __shared__ int    w0s[NA];

    const int tid  = threadIdx.x;
    const int pair = blockIdx.z;
    const int x0   = blockIdx.x * 32;
    const int y0   = blockIdx.y * 16;

    const int lane = tid & 31;
    const int w    = tid >> 5;
    const int x    = ((w & 3) << 3) + (lane & 7);        // 0..31
    const int yb   = (lane >> 3) + ((w >> 2) << 2);      // 0..7 (slots yb, yb+8)

    const int b0 = 2 * pair, b1 = 2 * pair + 1;
    const float invh = 2.0f / 511.0f;

    // ---- early out: tile fully outside the unit circle ----
    {
        float ux0 = fmaf((float)x0,        invh, -1.0f);
        float ux1 = fmaf((float)(x0 + 31), invh, -1.0f);
        float uy0 = fmaf((float)y0,        invh, -1.0f);
        float uy1 = fmaf((float)(y0 + 15), invh, -1.0f);
        float mx = (ux0 <= 0.0f && ux1 >= 0.0f) ? 0.0f : fminf(fabsf(ux0), fabsf(ux1));
        float my = (uy0 <= 0.0f && uy1 >= 0.0f) ? 0.0f : fminf(fabsf(uy0), fabsf(uy1));
        if (mx * mx + my * my > 1.0f) {
            #pragma unroll
            for (int k = 0; k < 2; ++k) {
                int y = y0 + yb + 8 * k;
                out[(b0 * S + y) * S + x0 + x] = 0.0f;
                out[(b1 * S + y) * S + x0 + x] = 0.0f;
            }
            return;
        }
    }

    // ---- per-angle tables ----
    if (tid < NA) {
        float th = (float)tid * (float)(PI_D / 180.0);
        float sn, cs;
        sincosf(th, &sn, &cs);
        float pb = 255.5f + ((float)x0 - 255.5f) * cs - ((float)y0 - 255.5f) * sn;
        float pmin = pb + fminf(cs * 31.0f, 0.0f) + fminf(-sn * 15.0f, 0.0f);
        int w0 = (int)floorf(pmin) - 1;          // local p in [1, ~36.5)
        w0s[tid] = w0;
        float ns = -sn;
        consA[tid] = make_float4(cs, pb - (float)w0 + 1024.0f, ns, 8.0f * ns);
    }
    __syncthreads();

    const float FX = (float)x;
    const float FY = (float)yb;

    // addr = (bits>>13)*8 + wb ; bits>>13 = 0x22400 + idx -> wb0 = base - 0x112000
    const unsigned wbadj = (unsigned)__cvta_generic_to_shared(winh) - 0x112000u;
    const unsigned cA0 = (unsigned)__cvta_generic_to_shared(consA);

    unsigned long long accE0 = 0, accE1 = 0;    // packed {E_b0, E_b1} per slot
    float aF00 = 0.f, aF01 = 0.f;               // slot0: fm*d accums per batch
    float aF10 = 0.f, aF11 = 0.f;               // slot1

    const uint2* __restrict__ gw = &g_xfh[pair * NA * S];

    const int al = (tid < 228) ? tid / WS : 0;     // 0..5
    const int oo = tid - al * WS;

    #pragma unroll 1
    for (int phase = 0; phase < 2; ++phase) {
        const int abase = phase * HALF_A;

        // ---- cooperative window fill (straight uint2 copy) ----
        if (tid < 228) {
            #pragma unroll
            for (int ar = al; ar < HALF_A; ar += 6) {
                int a  = abase + ar;
                int gi = w0s[a] + oo;
                uint2 v;
                if ((unsigned)gi < (unsigned)S) {
                    v = gw[a * S + gi];
                } else if (gi == -1) {
                    // bin -1 interpolates 0 -> w[0]:  d = rn(w0), em = rn(0.5*d)
                    uint2 v0 = gw[a * S];
                    __half2 e2 = *(__half2*)&v0.x;
                    __half2 d2 = *(__half2*)&v0.y;
                    float w00 = __low2float(e2)  - 0.5f * __low2float(d2);
                    float w01 = __high2float(e2) - 0.5f * __high2float(d2);
                    __half2 nd = __floats2half2_rn(w00, w01);
                    __half2 ne = __floats2half2_rn(0.5f * __low2float(nd),
                                                   0.5f * __high2float(nd));
                    v.x = *(unsigned*)&ne;
                    v.y = *(unsigned*)&nd;
                } else {
                    v.x = 0u; v.y = 0u;
                }
                winh[ar * WS + oo] = v;
            }
        }
        __syncthreads();

        unsigned caA = cA0 + (unsigned)abase * 16u;
        unsigned wb  = wbadj;                      // per-angle window base

        #pragma unroll 3
        for (int a = 0; a < HALF_A; ++a) {
            unsigned a0, a1;
            float fm0, fm1;

            // ---- scalar front-end: biased p -> addr + f32 (fr-0.5) ----
            asm("{\n\t"
                ".reg .f32 cs, czb, ns, ns8, bx, p0f, p1f, ft;\n\t"
                ".reg .b32 rb0, rb1, rt;\n\t"
                "ld.shared.v4.f32 {cs, czb, ns, ns8}, [%4];\n\t"
                "fma.rn.f32 bx, cs, %5, czb;\n\t"
                "fma.rn.f32 p0f, ns, %6, bx;\n\t"
                "add.rn.f32 p1f, p0f, ns8;\n\t"
                "mov.b32 rb0, p0f;\n\t"
                "mov.b32 rb1, p1f;\n\t"
                "shr.u32 rt, rb0, 13;\n\t"
                "mad.lo.u32 %0, rt, 8, %7;\n\t"
                "shr.u32 rt, rb1, 13;\n\t"
                "mad.lo.u32 %1, rt, 8, %7;\n\t"
                "shl.b32 rt, rb0, 10;\n\t"
                "lop3.b32 rt, rt, 0x007FFC00, 0x3F800000, 0xEA;\n\t"
                "mov.b32 ft, rt;\n\t"
                "sub.rn.f32 %2, ft, 0f3FC00000;\n\t"    // (1+fr) - 1.5
                "shl.b32 rt, rb1, 10;\n\t"
                "lop3.b32 rt, rt, 0x007FFC00, 0x3F800000, 0xEA;\n\t"
                "mov.b32 ft, rt;\n\t"
                "sub.rn.f32 %3, ft, 0f3FC00000;\n\t"
                "}"
                : "=&r"(a0), "=&r"(a1), "=&f"(fm0), "=&f"(fm1)
                : "r"(caA), "f"(FX), "f"(FY), "r"(wb));

            // ---- 2 loads back-to-back ----
            unsigned E0, D0, E1, D1;
            asm volatile("ld.shared.v2.b32 {%0, %1}, [%2];" : "=r"(E0), "=r"(D0) : "r"(a0));
            asm volatile("ld.shared.v2.b32 {%0, %1}, [%2];" : "=r"(E1), "=r"(D1) : "r"(a1));

            // ---- f32 interpolate: packed E accumulate, scalar F fma ----
#define SLOT_ACC(FM, EE, DD, ACCE, AF0, AF1)                                  \
            asm("{\n\t"                                                       \
                ".reg .b16 hl, hh;\n\t"                                       \
                ".reg .f32 f0, f1, g0, g1;\n\t"                               \
                ".reg .b64 eP;\n\t"                                           \
                "mov.b32 {hl, hh}, %3;\n\t"                                   \
                "cvt.f32.f16 f0, hl;\n\t"                                     \
                "cvt.f32.f16 f1, hh;\n\t"                                     \
                "mov.b64 eP, {f0, f1};\n\t"                                   \
                "add.rn.f32x2 %0, %0, eP;\n\t"                                \
                "mov.b32 {hl, hh}, %4;\n\t"                                   \
                "cvt.f32.f16 g0, hl;\n\t"                                     \
                "cvt.f32.f16 g1, hh;\n\t"                                     \
                "fma.rn.f32 %1, %5, g0, %1;\n\t"                              \
                "fma.rn.f32 %2, %5, g1, %2;\n\t"                              \
                "}"                                                           \
                : "+l"(ACCE), "+f"(AF0), "+f"(AF1)                            \
                : "r"(EE), "r"(DD), "f"(FM));

            SLOT_ACC(fm0, E0, D0, accE0, aF00, aF01)
            SLOT_ACC(fm1, E1, D1, accE1, aF10, aF11)
#undef SLOT_ACC

            caA += 16u;
            wb  += (unsigned)(WS * 8);             // advance one window row
        }
        __syncthreads();
    }

    // ---- unpack, mask, scale, store (both batches) ----
    const float scale = (float)(PI_D / (2.0 * NA));
    const float ux  = fmaf((float)(x0 + x), invh, -1.0f);
    const float uxx = ux * ux;

    {
        float e0, e1;
        asm("mov.b64 {%0, %1}, %2;" : "=f"(e0), "=f"(e1) : "l"(accE0));
        int y = y0 + yb;
        float uy = fmaf((float)y, invh, -1.0f);
        bool in = (uxx + uy * uy <= 1.0f);
        out[(b0 * S + y) * S + x0 + x] = in ? (e0 + aF00) * scale : 0.0f;
        out[(b1 * S + y) * S + x0 + x] = in ? (e1 + aF01) * scale : 0.0f;
    }
    {
        float e0, e1;
        asm("mov.b64 {%0, %1}, %2;" : "=f"(e0), "=f"(e1) : "l"(accE1));
        int y = y0 + yb + 8;
        float uy = fmaf((float)y, invh, -1.0f);
        bool in = (uxx + uy * uy <= 1.0f);
        out[(b0 * S + y) * S + x0 + x] = in ? (e0 + aF10) * scale : 0.0f;
        out[(b1 * S + y) * S + x0 + x] = in ? (e1 + aF11) * scale : 0.0f;
    }
}

// ---------------------------------------------------------------------------
extern "C" void kernel_launch(void* const* d_in, const int* in_sizes, int n_in,
                              void* d_out, int out_size) {
    const float* x = (const float*)d_in[0];
    float* out = (float*)d_out;

    filter_kernel<<<2 * NA, 128>>>(x);

    dim3 grid(16, 32, 2);
    backproj_kernel<<<grid, 256>>>(out);
}

// round 14
// speedup vs baseline: 2.0499x; 1.0659x over previous
#include <cuda_runtime.h>
#include <cuda_fp16.h>

#define S    512
#define NA   180
#define NB   4
#define WS   38
#define HALF_A 90
#define PI_D 3.14159265358979323846

// filtered sinogram, batch-pair fp16: [pair][a][s] = uint2 { half2{em0,em1}, half2{d0,d1} }
// d = rn16(w[s+1]-w[s]),  em = rn16(w[s] + 0.5*float(d))
// sample = em + (fr-0.5)*d = w + fr*d   (f32 arithmetic)
__device__ uint2 g_xfh[2 * NA * S];

// ---------------------------------------------------------------------------
// Stage 1: ramp filter. One block per (pair, a): 256 threads =
//   2 batch-halves (bh) x 2 tap-halves (th), each a 64-thread sliding FIR.
//   th=0: taps d=511..257 (+ center), th=1: taps d=255..1; summed via smem.
// ---------------------------------------------------------------------------
#define OFFM(d) ((d) + ((1 + (d)) >> 3))
#define OFFP(d) ((d) + ((7 + (d)) >> 3))

__global__ void __launch_bounds__(256) filter_kernel(const float* __restrict__ x) {
    const int a    = blockIdx.x % NA;
    const int pair = blockIdx.x / NA;

    __shared__ float P[2][1736];
    __shared__ float sg[256];
    __shared__ float sw[2][S + 8];
    __shared__ float sred[2][64][8];

    const int tid = threadIdx.x;
    const int t   = tid & 63;
    const int bh  = (tid >> 6) & 1;
    const int th  = tid >> 7;

    // zeros + data (all 256 threads, both batches)
    for (int idx = tid; idx < 1024; idx += 256) {
        int bb = idx >> 9, i = idx & 511;
        P[bb][i + (i >> 3)] = 0.0f;
        int j = i + 1024;
        P[bb][j + (j >> 3)] = 0.0f;
    }
    for (int idx = tid; idx < 1024; idx += 256) {
        int bb = idx >> 9, i = idx & 511;
        int ii = i + 512;
        P[bb][ii + (ii >> 3)] = x[((2 * pair + bb) * S + i) * NA + a];
    }
    {
        float dd = (float)(2 * tid + 1);
        sg[tid] = -2.0f / ((float)(PI_D * PI_D) * dd * dd);
    }
    __syncthreads();

    float* Pb = P[bh];
    float acc[8];
    if (th == 0) {
        #pragma unroll
        for (int k = 0; k < 8; ++k)
            acc[k] = 0.5f * Pb[9 * t + 576 + k];
    } else {
        #pragma unroll
        for (int k = 0; k < 8; ++k)
            acc[k] = 0.0f;
    }

    float Am[16], Ap[16];
    int A0 = 9 * t + 1 + 288 * th;
    int A1 = 9 * t + 1132 - 288 * th;
    const int sgb = 255 - 128 * th;

    #pragma unroll
    for (int d0 = 0; d0 < 8; ++d0) {
        Am[d0] = Pb[A0 + OFFM(d0)];
        Ap[d0] = Pb[A1 + OFFP(16 + d0)];
    }

    #pragma unroll 1
    for (int g = 0; g < 16; ++g) {
        #pragma unroll
        for (int jj = 0; jj < 8; ++jj) {
            float gc = sg[sgb - 8 * g - jj];
            #pragma unroll
            for (int k = 0; k < 8; ++k) {
                float av = Am[(2 * jj + k) & 15];
                float bv = Ap[(k - 2 * jj) & 15];
                acc[k] = fmaf(gc, av + bv, acc[k]);
            }
            Am[(2 * jj + 8) & 15]  = Pb[A0 + OFFM(2 * jj + 8)];
            Am[(2 * jj + 9) & 15]  = Pb[A0 + OFFM(2 * jj + 9)];
            Ap[(14 - 2 * jj) & 15] = Pb[A1 + OFFP(14 - 2 * jj)];
            Ap[(15 - 2 * jj) & 15] = Pb[A1 + OFFP(15 - 2 * jj)];
        }
        A0 += 18;
        A1 -= 18;
    }

    if (th == 1) {
        #pragma unroll
        for (int k = 0; k < 8; ++k)
            sred[bh][t][k] = acc[k];
    }
    __syncthreads();
    if (th == 0) {
        #pragma unroll
        for (int k = 0; k < 8; ++k)
            sw[bh][8 * t + k] = acc[k] + sred[bh][t][k];
        if (t == 0) sw[bh][S] = 0.0f;
    }
    __syncthreads();

    // coalesced epilogue: uint2 {em0,em1 | d0,d1}
    uint2* o = &g_xfh[(pair * NA + a) * S];
    #pragma unroll
    for (int s = tid; s < S; s += 256) {
        float lo0 = sw[0][s];
        float lo1 = sw[1][s];
        __half d0 = __float2half(sw[0][s + 1] - lo0);
        __half d1 = __float2half(sw[1][s + 1] - lo1);
        __half e0 = __float2half(fmaf(0.5f, __half2float(d0), lo0));
        __half e1 = __float2half(fmaf(0.5f, __half2float(d1), lo1));
        __half2 eh = __halves2half2(e0, e1);
        __half2 dh = __halves2half2(d0, d1);
        uint2 v;
        v.x = *(unsigned*)&eh;
        v.y = *(unsigned*)&dh;
        o[s] = v;
    }
}

// ---------------------------------------------------------------------------
// Stage 2: backprojection, fp16 storage / f32 arithmetic, packed E-accum,
// 6-angle unrolled chunks with immediate offsets.
// Grid (16,32,2): 32x16 tile x one batch PAIR. 256 threads, 2 y-slots each.
// ---------------------------------------------------------------------------
__global__ void __launch_bounds__(256, 6) backproj_kernel(float* __restrict__ out) {
    __shared__ uint2  winh[HALF_A * WS];     // 27360 B
    __shared__ float4 consA[NA];             // {cs, czb, ns, 8ns}
    __shared__ int    w0s[NA];

    const int tid  = threadIdx.x;
    const int pair = blockIdx.z;
    const int x0   = blockIdx.x * 32;
    const int y0   = blockIdx.y * 16;

    const int lane = tid & 31;
    const int w    = tid >> 5;
    const int x    = ((w & 3) << 3) + (lane & 7);        // 0..31
    const int yb   = (lane >> 3) + ((w >> 2) << 2);      // 0..7 (slots yb, yb+8)

    const int b0 = 2 * pair, b1 = 2 * pair + 1;
    const float invh = 2.0f / 511.0f;

    // ---- early out: tile fully outside the unit circle ----
    {
        float ux0 = fmaf((float)x0,        invh, -1.0f);
        float ux1 = fmaf((float)(x0 + 31), invh, -1.0f);
        float uy0 = fmaf((float)y0,        invh, -1.0f);
        float uy1 = fmaf((float)(y0 + 15), invh, -1.0f);
        float mx = (ux0 <= 0.0f && ux1 >= 0.0f) ? 0.0f : fminf(fabsf(ux0), fabsf(ux1));
        float my = (uy0 <= 0.0f && uy1 >= 0.0f) ? 0.0f : fminf(fabsf(uy0), fabsf(uy1));
        if (mx * mx + my * my > 1.0f) {
            #pragma unroll
            for (int k = 0; k < 2; ++k) {
                int y = y0 + yb + 8 * k;
                out[(b0 * S + y) * S + x0 + x] = 0.0f;
                out[(b1 * S + y) * S + x0 + x] = 0.0f;
            }
            return;
        }
    }

    // ---- per-angle tables ----
    if (tid < NA) {
        float th = (float)tid * (float)(PI_D / 180.0);
        float sn, cs;
        sincosf(th, &sn, &cs);
        float pb = 255.5f + ((float)x0 - 255.5f) * cs - ((float)y0 - 255.5f) * sn;
        float pmin = pb + fminf(cs * 31.0f, 0.0f) + fminf(-sn * 15.0f, 0.0f);
        int w0 = (int)floorf(pmin) - 1;          // local p in [1, ~36.5)
        w0s[tid] = w0;
        float ns = -sn;
        consA[tid] = make_float4(cs, pb - (float)w0 + 1024.0f, ns, 8.0f * ns);
    }
    __syncthreads();

    const float FX = (float)x;
    const float FY = (float)yb;

    // addr = (bits>>13)*8 + wb ; bits>>13 = 0x22400 + idx -> wb0 = base - 0x112000
    const unsigned wbadj = (unsigned)__cvta_generic_to_shared(winh) - 0x112000u;
    const unsigned cA0 = (unsigned)__cvta_generic_to_shared(consA);

    unsigned long long accE0 = 0, accE1 = 0;    // packed {E_b0, E_b1} per slot
    float aF00 = 0.f, aF01 = 0.f;               // slot0: fm*d accums per batch
    float aF10 = 0.f, aF11 = 0.f;               // slot1

    const uint2* __restrict__ gw = &g_xfh[pair * NA * S];

    const int al = (tid < 228) ? tid / WS : 0;     // 0..5
    const int oo = tid - al * WS;

#define SLOT_ACC(FM, EE, DD, ACCE, AF0, AF1)                                  \
            asm("{\n\t"                                                       \
                ".reg .b16 hl, hh;\n\t"                                       \
                ".reg .f32 f0, f1, g0, g1;\n\t"                               \
                ".reg .b64 eP;\n\t"                                           \
                "mov.b32 {hl, hh}, %3;\n\t"                                   \
                "cvt.f32.f16 f0, hl;\n\t"                                     \
                "cvt.f32.f16 f1, hh;\n\t"                                     \
                "mov.b64 eP, {f0, f1};\n\t"                                   \
                "add.rn.f32x2 %0, %0, eP;\n\t"                                \
                "mov.b32 {hl, hh}, %4;\n\t"                                   \
                "cvt.f32.f16 g0, hl;\n\t"                                     \
                "cvt.f32.f16 g1, hh;\n\t"                                     \
                "fma.rn.f32 %1, %5, g0, %1;\n\t"                              \
                "fma.rn.f32 %2, %5, g1, %2;\n\t"                              \
                "}"                                                           \
                : "+l"(ACCE), "+f"(AF0), "+f"(AF1)                            \
                : "r"(EE), "r"(DD), "f"(FM));

#define ANGLE(CIMM, WIMM)                                                     \
        {                                                                     \
            unsigned a0, a1;                                                  \
            float fm0, fm1;                                                   \
            asm("{\n\t"                                                       \
                ".reg .f32 cs, czb, ns, ns8, bx, p0f, p1f, ft;\n\t"           \
                ".reg .b32 rb0, rb1, rt;\n\t"                                 \
                "ld.shared.v4.f32 {cs, czb, ns, ns8}, [%4+" #CIMM "];\n\t"    \
                "fma.rn.f32 bx, cs, %5, czb;\n\t"                             \
                "fma.rn.f32 p0f, ns, %6, bx;\n\t"                             \
                "add.rn.f32 p1f, p0f, ns8;\n\t"                               \
                "mov.b32 rb0, p0f;\n\t"                                       \
                "mov.b32 rb1, p1f;\n\t"                                       \
                "shr.u32 rt, rb0, 13;\n\t"                                    \
                "mad.lo.u32 %0, rt, 8, %7;\n\t"                               \
                "shr.u32 rt, rb1, 13;\n\t"                                    \
                "mad.lo.u32 %1, rt, 8, %7;\n\t"                               \
                "shl.b32 rt, rb0, 10;\n\t"                                    \
                "lop3.b32 rt, rt, 0x007FFC00, 0x3F800000, 0xEA;\n\t"          \
                "mov.b32 ft, rt;\n\t"                                         \
                "sub.rn.f32 %2, ft, 0f3FC00000;\n\t"                          \
                "shl.b32 rt, rb1, 10;\n\t"                                    \
                "lop3.b32 rt, rt, 0x007FFC00, 0x3F800000, 0xEA;\n\t"          \
                "mov.b32 ft, rt;\n\t"                                         \
                "sub.rn.f32 %3, ft, 0f3FC00000;\n\t"                          \
                "}"                                                           \
                : "=&r"(a0), "=&r"(a1), "=&f"(fm0), "=&f"(fm1)                \
                : "r"(caA), "f"(FX), "f"(FY), "r"(wb));                       \
            unsigned E0, D0, E1, D1;                                          \
            asm volatile("ld.shared.v2.b32 {%0, %1}, [%2+" #WIMM "];"         \
                         : "=r"(E0), "=r"(D0) : "r"(a0));                     \
            asm volatile("ld.shared.v2.b32 {%0, %1}, [%2+" #WIMM "];"         \
                         : "=r"(E1), "=r"(D1) : "r"(a1));                     \
            SLOT_ACC(fm0, E0, D0, accE0, aF00, aF01)                          \
            SLOT_ACC(fm1, E1, D1, accE1, aF10, aF11)                          \
        }

    #pragma unroll 1
    for (int phase = 0; phase < 2; ++phase) {
        const int abase = phase * HALF_A;

        // ---- cooperative window fill (straight uint2 copy) ----
        if (tid < 228) {
            #pragma unroll
            for (int ar = al; ar < HALF_A; ar += 6) {
                int a  = abase + ar;
                int gi = w0s[a] + oo;
                uint2 v;
                if ((unsigned)gi < (unsigned)S) {
                    v = gw[a * S + gi];
                } else if (gi == -1) {
                    // bin -1 interpolates 0 -> w[0]:  d = rn(w0), em = rn(0.5*d)
                    uint2 v0 = gw[a * S];
                    __half2 e2 = *(__half2*)&v0.x;
                    __half2 d2 = *(__half2*)&v0.y;
                    float w00 = __low2float(e2)  - 0.5f * __low2float(d2);
                    float w01 = __high2float(e2) - 0.5f * __high2float(d2);
                    __half2 nd = __floats2half2_rn(w00, w01);
                    __half2 ne = __floats2half2_rn(0.5f * __low2float(nd),
                                                   0.5f * __high2float(nd));
                    v.x = *(unsigned*)&ne;
                    v.y = *(unsigned*)&nd;
                } else {
                    v.x = 0u; v.y = 0u;
                }
                winh[ar * WS + oo] = v;
            }
        }
        __syncthreads();

        unsigned caA = cA0 + (unsigned)abase * 16u;
        unsigned wb  = wbadj;

        #pragma unroll 1
        for (int ch = 0; ch < 15; ++ch) {      // 15 chunks x 6 angles = 90
            ANGLE(0,  0)
            ANGLE(16, 304)
            ANGLE(32, 608)
            ANGLE(48, 912)
            ANGLE(64, 1216)
            ANGLE(80, 1520)
            caA += 96u;
            wb  += 1824u;                       // 6 * WS * 8
        }
        __syncthreads();
    }
#undef ANGLE
#undef SLOT_ACC

    // ---- unpack, mask, scale, store (both batches) ----
    const float scale = (float)(PI_D / (2.0 * NA));
    const float ux  = fmaf((float)(x0 + x), invh, -1.0f);
    const float uxx = ux * ux;

    {
        float e0, e1;
        asm("mov.b64 {%0, %1}, %2;" : "=f"(e0), "=f"(e1) : "l"(accE0));
        int y = y0 + yb;
        float uy = fmaf((float)y, invh, -1.0f);
        bool in = (uxx + uy * uy <= 1.0f);
        out[(b0 * S + y) * S + x0 + x] = in ? (e0 + aF00) * scale : 0.0f;
        out[(b1 * S + y) * S + x0 + x] = in ? (e1 + aF01) * scale : 0.0f;
    }
    {
        float e0, e1;
        asm("mov.b64 {%0, %1}, %2;" : "=f"(e0), "=f"(e1) : "l"(accE1));
        int y = y0 + yb + 8;
        float uy = fmaf((float)y, invh, -1.0f);
        bool in = (uxx + uy * uy <= 1.0f);
        out[(b0 * S + y) * S + x0 + x] = in ? (e0 + aF10) * scale : 0.0f;
        out[(b1 * S + y) * S + x0 + x] = in ? (e1 + aF11) * scale : 0.0f;
    }
}

// ---------------------------------------------------------------------------
extern "C" void kernel_launch(void* const* d_in, const int* in_sizes, int n_in,
                              void* d_out, int out_size) {
    const float* x = (const float*)d_in[0];
    float* out = (float*)d_out;

    filter_kernel<<<2 * NA, 256>>>(x);

    dim3 grid(16, 32, 2);
    backproj_kernel<<<grid, 256>>>(out);
}